// round 1
// baseline (speedup 1.0000x reference)
#include <cuda_runtime.h>
#include <cstdint>

#define D_IN 64
#define D_EDGE 16
#define H 16
#define MAXN 102400

// Per-node scratch (static device allocs are allowed)
__device__ float g_xm[MAXN * H];    // x @ W_msg1[:64]
__device__ float g_sk1[MAXN * H];   // x @ W_skip1 + b_skip1
__device__ float g_agg1[MAXN * H];  // conv1 segment sum
__device__ float g_agg2[MAXN * H];  // conv2 segment sum (+ skip2)
__device__ float g_hm[MAXN * H];    // h1 @ W_msg2[:16]

__device__ __forceinline__ void red_add_v4(float* addr, float a, float b, float c, float d) {
    asm volatile("red.global.add.v4.f32 [%0], {%1, %2, %3, %4};"
                 :: "l"(addr), "f"(a), "f"(b), "f"(c), "f"(d) : "memory");
}

// ---------------------------------------------------------------------------
// Pass A: per node: xm = x @ Wm1[:64], sk1 = x @ Wsk1 + b_sk1 ; zero agg1/agg2
// 16 threads/node, 16 nodes/block (256 threads)
// ---------------------------------------------------------------------------
__global__ void pass_a(const float* __restrict__ x,
                       const float* __restrict__ Wm1,   // [80,16], use rows 0..63
                       const float* __restrict__ Wsk1,  // [64,16]
                       const float* __restrict__ bsk1,  // [16]
                       int N) {
    __shared__ float sWm[D_IN * H];
    __shared__ float sWs[D_IN * H];
    __shared__ float sb[H];
    __shared__ float sx[16 * D_IN];
    int tid = threadIdx.x;
    for (int i = tid; i < D_IN * H; i += 256) { sWm[i] = Wm1[i]; sWs[i] = Wsk1[i]; }
    if (tid < H) sb[tid] = bsk1[tid];
    int nbase = blockIdx.x * 16;
    for (int i = tid; i < 16 * D_IN; i += 256) {
        int n = nbase + (i >> 6);
        sx[i] = (n < N) ? x[(size_t)n * D_IN + (i & 63)] : 0.f;
    }
    __syncthreads();
    int ln = tid >> 4, j = tid & 15;
    int n = nbase + ln;
    if (n >= N) return;
    const float* xr = &sx[ln * D_IN];
    float a = 0.f, s = sb[j];
#pragma unroll
    for (int k = 0; k < D_IN; k++) {
        float xv = xr[k];
        a = fmaf(xv, sWm[k * H + j], a);
        s = fmaf(xv, sWs[k * H + j], s);
    }
    int o = n * H + j;
    g_xm[o] = a;
    g_sk1[o] = s;
    g_agg1[o] = 0.f;
    g_agg2[o] = 0.f;
}

// ---------------------------------------------------------------------------
// Pass B: per edge:
//   m1 = xm[src] + ea @ Wm1[64:80] + b1  --> red into agg1[dst]
//   m2 =           ea @ Wm2[16:32] + b2  --> red into agg2[dst]
// 4 threads/edge (each owns 4 output dims), 64 edges/block (256 threads)
// ---------------------------------------------------------------------------
#define EA_STRIDE 20
__global__ void pass_b(const int* __restrict__ ei,     // [2,E]
                       const float* __restrict__ ea,   // [E,16]
                       const float* __restrict__ Wm1,  // [80,16]
                       const float* __restrict__ b1,   // [16]
                       const float* __restrict__ Wm2,  // [32,16]
                       const float* __restrict__ b2,   // [16]
                       int E) {
    __shared__ float sW1[D_EDGE * H];
    __shared__ float sW2[D_EDGE * H];
    __shared__ float sb1[H], sb2[H];
    __shared__ float sEA[64 * EA_STRIDE];
    int tid = threadIdx.x;
    sW1[tid] = Wm1[D_IN * H + tid];    // rows 64..79
    sW2[tid] = Wm2[H * H + tid];       // rows 16..31
    if (tid < H) { sb1[tid] = b1[tid]; sb2[tid] = b2[tid]; }

    int le = tid >> 2, c = tid & 3;
    int e = blockIdx.x * 64 + le;
    bool valid = (e < E);
    if (valid) {
        float4 v = reinterpret_cast<const float4*>(ea)[(size_t)e * 4 + c];
        float* p = &sEA[le * EA_STRIDE + c * 4];
        p[0] = v.x; p[1] = v.y; p[2] = v.z; p[3] = v.w;
    }
    __syncthreads();
    if (!valid) return;

    int src = ei[e];
    int dst = ei[(size_t)E + e];

    float4 xm4 = reinterpret_cast<const float4*>(g_xm)[(size_t)src * 4 + c];
    int jb = c * 4;
    float m1x = xm4.x + sb1[jb + 0], m1y = xm4.y + sb1[jb + 1];
    float m1z = xm4.z + sb1[jb + 2], m1w = xm4.w + sb1[jb + 3];
    float m2x = sb2[jb + 0], m2y = sb2[jb + 1], m2z = sb2[jb + 2], m2w = sb2[jb + 3];

    const float* er = &sEA[le * EA_STRIDE];
#pragma unroll
    for (int k = 0; k < D_EDGE; k++) {
        float ev = er[k];
        const float* w1 = &sW1[k * H + jb];
        const float* w2 = &sW2[k * H + jb];
        m1x = fmaf(ev, w1[0], m1x); m1y = fmaf(ev, w1[1], m1y);
        m1z = fmaf(ev, w1[2], m1z); m1w = fmaf(ev, w1[3], m1w);
        m2x = fmaf(ev, w2[0], m2x); m2y = fmaf(ev, w2[1], m2y);
        m2z = fmaf(ev, w2[2], m2z); m2w = fmaf(ev, w2[3], m2w);
    }
    red_add_v4(&g_agg1[(size_t)dst * H + jb], m1x, m1y, m1z, m1w);
    red_add_v4(&g_agg2[(size_t)dst * H + jb], m2x, m2y, m2z, m2w);
}

// ---------------------------------------------------------------------------
// Pass C: per node: h1 = relu(agg1 + sk1); hm = h1 @ Wm2[:16];
//         agg2 += h1 @ Wsk2 + b_sk2
// 16 threads/node, 16 nodes/block
// ---------------------------------------------------------------------------
__global__ void pass_c(const float* __restrict__ Wm2,   // [32,16], rows 0..15
                       const float* __restrict__ Wsk2,  // [16,16]
                       const float* __restrict__ bsk2,  // [16]
                       int N) {
    __shared__ float sWm[H * H];
    __shared__ float sWs[H * H];
    __shared__ float sb[H];
    __shared__ float sh[16 * 17];
    int tid = threadIdx.x;
    sWm[tid] = Wm2[tid];
    sWs[tid] = Wsk2[tid];
    if (tid < H) sb[tid] = bsk2[tid];
    int ln = tid >> 4, j = tid & 15;
    int n = blockIdx.x * 16 + ln;
    float h = 0.f;
    if (n < N) {
        int o = n * H + j;
        h = fmaxf(g_agg1[o] + g_sk1[o], 0.f);
    }
    sh[ln * 17 + j] = h;
    __syncthreads();
    if (n >= N) return;
    const float* hr = &sh[ln * 17];
    float hm = 0.f, sk = sb[j];
#pragma unroll
    for (int k = 0; k < H; k++) {
        float hv = hr[k];
        hm = fmaf(hv, sWm[k * H + j], hm);
        sk = fmaf(hv, sWs[k * H + j], sk);
    }
    int o = n * H + j;
    g_hm[o] = hm;
    g_agg2[o] += sk;
}

// ---------------------------------------------------------------------------
// Pass D: per edge: agg2[dst] += hm[src]   (4 threads/edge, red.v4)
// ---------------------------------------------------------------------------
__global__ void pass_d(const int* __restrict__ ei, int E) {
    int t = blockIdx.x * 256 + threadIdx.x;
    int e = t >> 2, c = t & 3;
    if (e >= E) return;
    int src = ei[e];
    int dst = ei[(size_t)E + e];
    float4 v = reinterpret_cast<const float4*>(g_hm)[(size_t)src * 4 + c];
    red_add_v4(&g_agg2[(size_t)dst * H + c * 4], v.x, v.y, v.z, v.w);
}

// ---------------------------------------------------------------------------
// Pass E: per node: out = agg2 @ Wl3 + bl3   (64 threads/node, 4 nodes/block)
// ---------------------------------------------------------------------------
__global__ void pass_e(const float* __restrict__ Wl3,  // [16,64]
                       const float* __restrict__ bl3,  // [64]
                       float* __restrict__ out, int N) {
    __shared__ float sW[H * D_IN];
    __shared__ float sb[D_IN];
    int tid = threadIdx.x;
    for (int i = tid; i < H * D_IN; i += 256) sW[i] = Wl3[i];
    if (tid < D_IN) sb[tid] = bl3[tid];
    __syncthreads();
    int ln = tid >> 6, d = tid & 63;
    int n = blockIdx.x * 4 + ln;
    if (n >= N) return;
    const float* h2 = &g_agg2[(size_t)n * H];
    float acc = sb[d];
#pragma unroll
    for (int k = 0; k < H; k++) acc = fmaf(__ldg(&h2[k]), sW[k * D_IN + d], acc);
    out[(size_t)n * D_IN + d] = acc;
}

// ---------------------------------------------------------------------------
extern "C" void kernel_launch(void* const* d_in, const int* in_sizes, int n_in,
                              void* d_out, int out_size) {
    const float* x      = (const float*)d_in[0];
    const int*   ei     = (const int*)d_in[1];
    const float* ea     = (const float*)d_in[2];
    const float* Wm1    = (const float*)d_in[3];
    const float* bm1    = (const float*)d_in[4];
    const float* Wsk1   = (const float*)d_in[5];
    const float* bsk1   = (const float*)d_in[6];
    const float* Wm2    = (const float*)d_in[7];
    const float* bm2    = (const float*)d_in[8];
    const float* Wsk2   = (const float*)d_in[9];
    const float* bsk2   = (const float*)d_in[10];
    const float* Wl3    = (const float*)d_in[11];
    const float* bl3    = (const float*)d_in[12];
    float* out = (float*)d_out;

    int N = in_sizes[0] / D_IN;
    int E = in_sizes[1] / 2;

    int nb16 = (N + 15) / 16;
    int eb64 = (E + 63) / 64;

    pass_a<<<nb16, 256>>>(x, Wm1, Wsk1, bsk1, N);
    pass_b<<<eb64, 256>>>(ei, ea, Wm1, bm1, Wm2, bm2, E);
    pass_c<<<nb16, 256>>>(Wm2, Wsk2, bsk2, N);
    pass_d<<<eb64, 256>>>(ei, E);
    pass_e<<<(N + 3) / 4, 256>>>(Wl3, bl3, out, N);
}